// round 3
// baseline (speedup 1.0000x reference)
#include <cuda_runtime.h>
#include <math.h>

typedef unsigned long long u64;

// Problem constants (fixed by the reference generator)
#define SEQ_LEN   65536
#define NN        256      // num nodes
#define NC        32       // num causes (roots)
#define LW        16       // nodes per layer
#define NL        14       // layers
#define NF        200      // X features
#define ROWS      128      // sequence rows per CTA
#define NTHREADS  512      // 16 warps: 128 rows x 4 col-groups
#define VSTRIDE   129      // padded row stride for vals: bank = (node + row) % 32

#define SMEM_FLOATS (NN * VSTRIDE /*vals*/ + 240 * LW /*W stage*/)
#define SMEM_BYTES  (SMEM_FLOATS * 4 + NN * 4 /*acts*/ + NF * 4 /*x_idx*/)

__device__ __forceinline__ u64 pack2(float a, float b) {
    u64 r; asm("mov.b64 %0, {%1, %2};" : "=l"(r) : "f"(a), "f"(b)); return r;
}
__device__ __forceinline__ u64 splat2(float a) {
    u64 r; asm("mov.b64 %0, {%1, %1};" : "=l"(r) : "f"(a)); return r;
}
__device__ __forceinline__ void unpack2(u64 p, float& a, float& b) {
    asm("mov.b64 {%0, %1}, %2;" : "=f"(a), "=f"(b) : "l"(p));
}
__device__ __forceinline__ u64 fma2(u64 a, u64 b, u64 c) {
    u64 d; asm("fma.rn.f32x2 %0, %1, %2, %3;" : "=l"(d) : "l"(a), "l"(b), "l"(c)); return d;
}

__global__ __launch_bounds__(NTHREADS, 1)
void scm_kernel(const float* __restrict__ causes,
                const float* __restrict__ W,
                const float* __restrict__ eps,
                const int*   __restrict__ act_ids,
                const int*   __restrict__ x_idx,
                const int*   __restrict__ y_idx_p,
                float*       __restrict__ out)
{
    extern __shared__ float smem[];
    float* Vs   = smem;                        // [NN][VSTRIDE]
    float* Ws   = Vs + NN * VSTRIDE;           // [P][16], P <= 240
    int*   acts = (int*)(Ws + 240 * LW);       // [NN]
    int*   xs   = acts + NN;                   // [NF]

    const int tid  = threadIdx.x;
    const int row  = tid & (ROWS - 1);         // 0..127 (warp = 32 consecutive rows)
    const int cg   = tid >> 7;                 // 0..3: which 4 of the 16 layer outputs
    const int row0 = blockIdx.x * ROWS;
    const int rowg = row0 + row;

    if (tid < NN) acts[tid] = act_ids[tid];
    if (tid < NF) xs[tid]   = x_idx[tid];

    // Roots: vals[:, 0:32] = clip(causes, -5, 5)
    for (int idx = tid; idx < ROWS * NC; idx += NTHREADS) {
        int r = idx >> 5, c = idx & 31;
        float v = causes[(size_t)(row0 + r) * NC + c];
        v = fminf(fmaxf(v, -5.f), 5.f);
        Vs[c * VSTRIDE + r] = v;
    }
    __syncthreads();

    const int cbase = cg * 4;

    for (int k = 0; k < NL; ++k) {
        const int P        = NC + k * LW;      // parents span nodes [0, P)
        const int nodebase = NC + k * LW;

        // Stage W[0:P, nodebase:nodebase+16] -> Ws[p*16 + c]
        for (int idx = tid; idx < P * LW; idx += NTHREADS) {
            int p = idx >> 4, c = idx & 15;
            Ws[idx] = W[p * NN + nodebase + c];
        }
        __syncthreads();

        // acc = eps slice for this row's 4 output nodes (packed f32x2 pairs)
        u64 acc01, acc23;
        {
            float4 e0 = *(const float4*)(eps + (size_t)rowg * NN + nodebase + cbase);
            acc01 = pack2(e0.x, e0.y);
            acc23 = pack2(e0.z, e0.w);
        }

        const float* Wbase = Ws + cbase;       // this colgroup's 4 columns
        #pragma unroll 8
        for (int p = 0; p < P; ++p) {
            float v  = Vs[p * VSTRIDE + row];              // conflict-free: bank=(p+row)%32
            u64   v2 = splat2(v);
            ulonglong2 w = *(const ulonglong2*)(Wbase + (p << 4));  // LDS.128, warp-broadcast
            acc01 = fma2(v2, w.x, acc01);
            acc23 = fma2(v2, w.y, acc23);
        }

        float z[4];
        unpack2(acc01, z[0], z[1]);
        unpack2(acc23, z[2], z[3]);

        // Activation + write back
        #pragma unroll
        for (int i = 0; i < 4; ++i) {
            int   node = nodebase + cbase + i;
            int   aid  = acts[node];
            float zz = z[i], a;
            if      (aid == 0) a = zz;
            else if (aid == 1) a = tanhf(zz);
            else if (aid == 2) a = fmaxf(zz, 0.f);
            else               a = 1.f / (1.f + expf(-zz));
            Vs[node * VSTRIDE + row] = a;
        }
        __syncthreads();
    }

    // Outputs: X = clip(nan_to_num(vals[:, x_idx]), -15, 15) then y = nan_to_num(vals[:, y_idx])
    const int yidx = y_idx_p ? *y_idx_p : (NN - 1);
    float* Xout = out;
    float* yout = out + (size_t)SEQ_LEN * NF;

    if (tid < ROWS) {
        float v = Vs[yidx * VSTRIDE + tid];
        if (v != v) v = 0.f;
        yout[row0 + tid] = v;
    }
    for (int idx = tid; idx < ROWS * NF; idx += NTHREADS) {
        int r = idx / NF, j = idx - r * NF;
        float v = Vs[xs[j] * VSTRIDE + r];
        if (v != v) v = 0.f;
        v = fminf(fmaxf(v, -15.f), 15.f);
        Xout[(size_t)(row0 + r) * NF + j] = v;
    }
}

extern "C" void kernel_launch(void* const* d_in, const int* in_sizes, int n_in,
                              void* d_out, int out_size)
{
    const float* causes  = (const float*)d_in[0];
    const float* W       = (const float*)d_in[1];
    const float* eps     = (const float*)d_in[2];
    const int*   act_ids = (const int*)d_in[3];
    const int*   x_idx   = (const int*)d_in[4];
    const int*   y_idx_p = (n_in > 5) ? (const int*)d_in[5] : nullptr;
    float*       out     = (float*)d_out;

    cudaFuncSetAttribute(scm_kernel, cudaFuncAttributeMaxDynamicSharedMemorySize, SMEM_BYTES);

    dim3 grid(SEQ_LEN / ROWS);   // 512 CTAs
    dim3 block(NTHREADS);
    scm_kernel<<<grid, block, SMEM_BYTES>>>(causes, W, eps, act_ids, x_idx, y_idx_p, out);
    (void)in_sizes; (void)out_size;
}

// round 5
// speedup vs baseline: 1.2403x; 1.2403x over previous
#include <cuda_runtime.h>
#include <cuda_fp16.h>
#include <math.h>
#include <stdint.h>

// ---------------- problem constants ----------------
#define SEQ_LEN   65536
#define NN        256
#define NC        32
#define LW        16
#define NL        14
#define NF        200
#define ROWS      128      // M per CTA
#define NTHREADS  256      // 8 warps x 16 rows each
#define AS        264      // A row stride in fp16 elems (528 B) -> conflict-free ldmatrix

// ---------------- smem map (bytes) ----------------
#define OFF_ACTS  0                         // 256 ints
#define OFF_XS    1024                      // 200 ints
#define OFF_BP    2048                      // 2 buffers x (hi + lo), stride 24 words/row
#define BPROW     24                        // u32 words per kk-row (16 used + pad)
#define BPHALF    (128 * BPROW * 4)         // 12288 B
#define BPBUF     (2 * BPHALF)              // hi + lo
#define OFF_AHI   (OFF_BP + 2 * BPBUF)      // 51200
#define ABYTES    (ROWS * AS * 2)           // 67584
#define OFF_ALO   (OFF_AHI + ABYTES)
#define SMEM_BYTES (OFF_ALO + ABYTES)       // 186368

// ---------------- helpers ----------------
__device__ __forceinline__ uint32_t smem_u32(const void* p) {
    uint32_t a;
    asm("{ .reg .u64 t; cvta.to.shared.u64 t, %1; cvt.u32.u64 %0, t; }" : "=r"(a) : "l"(p));
    return a;
}
__device__ __forceinline__ void ldsm_x4(uint32_t a[4], uint32_t addr) {
    asm volatile("ldmatrix.sync.aligned.m8n8.x4.shared.b16 {%0,%1,%2,%3}, [%4];"
        : "=r"(a[0]), "=r"(a[1]), "=r"(a[2]), "=r"(a[3]) : "r"(addr));
}
__device__ __forceinline__ void mma16816(float c[4], const uint32_t a[4], const uint32_t b[2]) {
    asm volatile("mma.sync.aligned.m16n8k16.row.col.f32.f16.f16.f32 "
        "{%0,%1,%2,%3}, {%4,%5,%6,%7}, {%8,%9}, {%0,%1,%2,%3};"
        : "+f"(c[0]), "+f"(c[1]), "+f"(c[2]), "+f"(c[3])
        : "r"(a[0]), "r"(a[1]), "r"(a[2]), "r"(a[3]), "r"(b[0]), "r"(b[1]));
}
// fp32 -> fp16 hi/lo split (2-term); hi+lo reproduces v to ~2^-22 rel
__device__ __forceinline__ void split16(float v, uint16_t& h, uint16_t& l) {
    __half hh = __float2half_rn(v);
    float  r  = v - __half2float(hh);
    __half ll = __float2half_rn(r);
    h = __half_as_ushort(hh);
    l = __half_as_ushort(ll);
}
__device__ __forceinline__ float actf(int aid, float z) {
    if (aid == 0) return z;
    if (aid == 1) return tanhf(z);
    if (aid == 2) return fmaxf(z, 0.f);
    return 1.f / (1.f + expf(-z));
}
__device__ __forceinline__ float readA(const char* hi, const char* lo, int m, int node) {
    uint32_t b = (uint32_t)m * (AS * 2) + (uint32_t)node * 2;
    return __half2float(*(const __half*)(hi + b)) + __half2float(*(const __half*)(lo + b));
}

__global__ __launch_bounds__(NTHREADS, 1)
void scm_kernel(const float* __restrict__ causes,
                const float* __restrict__ W,
                const float* __restrict__ eps,
                const int*   __restrict__ act_ids,
                const int*   __restrict__ x_idx,
                const int*   __restrict__ y_idx_p,
                float*       __restrict__ out)
{
    extern __shared__ char smem[];
    const uint32_t sb = smem_u32(smem);
    int*  acts = (int*)(smem + OFF_ACTS);
    int*  xs   = (int*)(smem + OFF_XS);
    char* Ahi  = smem + OFF_AHI;
    char* Alo  = smem + OFF_ALO;

    const int tid  = threadIdx.x;
    const int wid  = tid >> 5;
    const int lane = tid & 31;
    const int g    = lane >> 2;       // 0..7
    const int tig  = lane & 3;        // 0..3
    const int R    = wid * 16;        // this warp's 16 rows
    const int row0 = blockIdx.x * ROWS;

    if (tid < NN) acts[tid] = act_ids[tid];
    if (tid < NF) xs[tid]   = x_idx[tid];

    // ---- roots: A[:, 0:32] = hi/lo split of clip(causes, -5, 5) ----
    {
        int m = tid >> 1, h = tid & 1;          // each thread: 16 cols
        const float4* c4 = (const float4*)(causes + (size_t)(row0 + m) * NC + h * 16);
        float4 a = c4[0], b = c4[1], c = c4[2], d = c4[3];
        float v[16] = { a.x,a.y,a.z,a.w, b.x,b.y,b.z,b.w, c.x,c.y,c.z,c.w, d.x,d.y,d.z,d.w };
        uint32_t whi[8], wlo[8];
        #pragma unroll
        for (int i = 0; i < 8; ++i) {
            uint16_t h0, l0, h1, l1;
            float v0 = fminf(fmaxf(v[2*i],   -5.f), 5.f);
            float v1 = fminf(fmaxf(v[2*i+1], -5.f), 5.f);
            split16(v0, h0, l0); split16(v1, h1, l1);
            whi[i] = (uint32_t)h0 | ((uint32_t)h1 << 16);
            wlo[i] = (uint32_t)l0 | ((uint32_t)l1 << 16);
        }
        uint32_t base = (uint32_t)m * (AS * 2) + (uint32_t)h * 32;
        *(uint4*)(Ahi + base)      = make_uint4(whi[0], whi[1], whi[2], whi[3]);
        *(uint4*)(Ahi + base + 16) = make_uint4(whi[4], whi[5], whi[6], whi[7]);
        *(uint4*)(Alo + base)      = make_uint4(wlo[0], wlo[1], wlo[2], wlo[3]);
        *(uint4*)(Alo + base + 16) = make_uint4(wlo[4], wlo[5], wlo[6], wlo[7]);
    }

    // ---- stage layer-0 W into Bp buffer 0 ----
    {
        char* bHi = smem + OFF_BP;
        char* bLo = bHi + BPHALF;
        for (int e = tid; e < NC * 16; e += NTHREADS) {
            int p = e >> 4, n = e & 15;
            uint16_t h, l; split16(W[(size_t)p * NN + NC + n], h, l);
            uint32_t byte = (((uint32_t)(p >> 1) * BPROW + n) << 2) + ((p & 1) << 1);
            *(uint16_t*)(bHi + byte) = h;
            *(uint16_t*)(bLo + byte) = l;
        }
    }
    __syncthreads();

    const uint32_t a_addr = sb + OFF_AHI
                          + (uint32_t)(R + (lane & 15)) * (AS * 2)
                          + (uint32_t)((lane >> 4) * 8) * 2;

    for (int k = 0; k < NL; ++k) {
        const int nb  = NC + k * LW;
        const int nch = nb >> 4;                 // K/16

        // prefetch next layer's W into regs (hides LDG latency behind MMAs)
        float wpre[15];
        int   npre = 0;
        if (k < NL - 1) {
            const int Pn = nb + LW;
            for (int e = tid; e < Pn * 16; e += NTHREADS)
                wpre[npre++] = W[(size_t)(e >> 4) * NN + (nb + LW) + (e & 15)];
        }
        // prefetch eps for this layer's outputs
        float2 ev[4];
        #pragma unroll
        for (int t = 0; t < 2; ++t)
            #pragma unroll
            for (int hh = 0; hh < 2; ++hh)
                ev[t*2+hh] = *(const float2*)(eps + (size_t)(row0 + R + g + hh*8) * NN
                                              + nb + t*8 + 2*tig);

        const uint32_t* bpw = (const uint32_t*)(smem + OFF_BP + (k & 1) * BPBUF);
        const uint32_t* bpl = bpw + BPHALF / 4;

        float c0[4] = {0,0,0,0}, c1[4] = {0,0,0,0};
        for (int j = 0; j < nch; ++j) {
            uint32_t ahi[4], alo[4];
            ldsm_x4(ahi, a_addr + j * 32);
            ldsm_x4(alo, a_addr + ABYTES + j * 32);
            const int kk = j * 8 + tig;
            uint32_t bh0[2], bh1[2], bl0[2], bl1[2];
            bh0[0] = bpw[kk * BPROW + g];           bh0[1] = bpw[(kk + 4) * BPROW + g];
            bh1[0] = bpw[kk * BPROW + 8 + g];       bh1[1] = bpw[(kk + 4) * BPROW + 8 + g];
            bl0[0] = bpl[kk * BPROW + g];           bl0[1] = bpl[(kk + 4) * BPROW + g];
            bl1[0] = bpl[kk * BPROW + 8 + g];       bl1[1] = bpl[(kk + 4) * BPROW + 8 + g];
            mma16816(c0, ahi, bh0);  mma16816(c1, ahi, bh1);   // hh
            mma16816(c0, ahi, bl0);  mma16816(c1, ahi, bl1);   // hl
            mma16816(c0, alo, bh0);  mma16816(c1, alo, bh1);   // lh
        }

        // epilogue: z = C + eps, activation, hi/lo split, store back to A
        #pragma unroll
        for (int t = 0; t < 2; ++t) {
            float* c = t ? c1 : c0;
            const int col0 = nb + t * 8 + 2 * tig;
            const int aid0 = acts[col0], aid1 = acts[col0 + 1];
            float z0 = c[0] + ev[t*2].x,   z1 = c[1] + ev[t*2].y;      // row R+g
            float z2 = c[2] + ev[t*2+1].x, z3 = c[3] + ev[t*2+1].y;    // row R+g+8
            float a0 = actf(aid0, z0), a1 = actf(aid1, z1);
            float a2 = actf(aid0, z2), a3 = actf(aid1, z3);
            uint16_t h0,l0,h1,l1,h2,l2,h3,l3;
            split16(a0,h0,l0); split16(a1,h1,l1); split16(a2,h2,l2); split16(a3,h3,l3);
            uint32_t b0 = (uint32_t)(R + g)     * (AS * 2) + (uint32_t)col0 * 2;
            uint32_t b1 = (uint32_t)(R + g + 8) * (AS * 2) + (uint32_t)col0 * 2;
            *(uint32_t*)(Ahi + b0) = (uint32_t)h0 | ((uint32_t)h1 << 16);
            *(uint32_t*)(Alo + b0) = (uint32_t)l0 | ((uint32_t)l1 << 16);
            *(uint32_t*)(Ahi + b1) = (uint32_t)h2 | ((uint32_t)h3 << 16);
            *(uint32_t*)(Alo + b1) = (uint32_t)l2 | ((uint32_t)l3 << 16);
        }

        // store prefetched W into the other Bp buffer
        if (k < NL - 1) {
            char* bHi = smem + OFF_BP + ((k + 1) & 1) * BPBUF;
            char* bLo = bHi + BPHALF;
            const int Pn = nb + LW;
            int i = 0;
            for (int e = tid; e < Pn * 16; e += NTHREADS) {
                int p = e >> 4, n = e & 15;
                uint16_t h, l; split16(wpre[i++], h, l);
                uint32_t byte = (((uint32_t)(p >> 1) * BPROW + n) << 2) + ((p & 1) << 1);
                *(uint16_t*)(bHi + byte) = h;
                *(uint16_t*)(bLo + byte) = l;
            }
        }
        __syncthreads();
    }

    // ---- outputs ----
    const int yidx = y_idx_p ? *y_idx_p : (NN - 1);
    float* Xout = out;
    float* yout = out + (size_t)SEQ_LEN * NF;

    if (tid < ROWS) {
        float v = readA(Ahi, Alo, tid, yidx);
        if (v != v) v = 0.f;
        yout[row0 + tid] = v;
    }
    for (int idx = tid; idx < ROWS * NF; idx += NTHREADS) {
        int r = idx / NF, j = idx - r * NF;
        float v = readA(Ahi, Alo, r, xs[j]);
        if (v != v) v = 0.f;
        v = fminf(fmaxf(v, -15.f), 15.f);
        Xout[(size_t)(row0 + r) * NF + j] = v;
    }
}

extern "C" void kernel_launch(void* const* d_in, const int* in_sizes, int n_in,
                              void* d_out, int out_size)
{
    const float* causes  = (const float*)d_in[0];
    const float* W       = (const float*)d_in[1];
    const float* eps     = (const float*)d_in[2];
    const int*   act_ids = (const int*)d_in[3];
    const int*   x_idx   = (const int*)d_in[4];
    const int*   y_idx_p = (n_in > 5) ? (const int*)d_in[5] : nullptr;
    float*       out     = (float*)d_out;

    cudaFuncSetAttribute(scm_kernel, cudaFuncAttributeMaxDynamicSharedMemorySize, SMEM_BYTES);

    scm_kernel<<<SEQ_LEN / ROWS, NTHREADS, SMEM_BYTES>>>(
        causes, W, eps, act_ids, x_idx, y_idx_p, out);
    (void)in_sizes; (void)out_size;
}

// round 7
// speedup vs baseline: 1.5137x; 1.2204x over previous
#include <cuda_runtime.h>
#include <cuda_fp16.h>
#include <math.h>
#include <stdint.h>

// ---------------- problem constants ----------------
#define SEQ_LEN   65536
#define NN        256
#define NC        32
#define LW        16
#define NL        14
#define NF        200
#define ROWS      128      // M per CTA
#define NTHREADS  256      // 8 warps x 16 rows each
#define AS        264      // A row stride in fp16 elems (528 B) -> conflict-free ldmatrix

// ---------------- smem map (bytes) ----------------
#define OFF_ACTS  0                         // 256 ints
#define OFF_XS    1024                      // 200 ints
#define OFF_BP    2048                      // 2 packed-W buffers x (hi + lo)
#define BPROW     24                        // u32 words per kk-row (16 used + pad)
#define BPHALF    (128 * BPROW * 4)         // 12288 B
#define BPBUF     (2 * BPHALF)
#define OFF_STAGE (OFF_BP + 2 * BPBUF)      // 2 x 16KB raw fp32 W stage (cp.async dst)
#define STAGEB    16384
#define OFF_AHI   (OFF_STAGE + 2 * STAGEB)
#define ABYTES    (ROWS * AS * 2)           // 67584
#define OFF_ALO   (OFF_AHI + ABYTES)
#define SMEM_BYTES (OFF_ALO + ABYTES)       // 219136

// ---------------- helpers ----------------
__device__ __forceinline__ uint32_t smem_u32(const void* p) {
    uint32_t a;
    asm("{ .reg .u64 t; cvta.to.shared.u64 t, %1; cvt.u32.u64 %0, t; }" : "=r"(a) : "l"(p));
    return a;
}
__device__ __forceinline__ void ldsm_x4(uint32_t a[4], uint32_t addr) {
    asm volatile("ldmatrix.sync.aligned.m8n8.x4.shared.b16 {%0,%1,%2,%3}, [%4];"
        : "=r"(a[0]), "=r"(a[1]), "=r"(a[2]), "=r"(a[3]) : "r"(addr));
}
__device__ __forceinline__ void mma16816(float c[4], const uint32_t a[4], const uint32_t b[2]) {
    asm volatile("mma.sync.aligned.m16n8k16.row.col.f32.f16.f16.f32 "
        "{%0,%1,%2,%3}, {%4,%5,%6,%7}, {%8,%9}, {%0,%1,%2,%3};"
        : "+f"(c[0]), "+f"(c[1]), "+f"(c[2]), "+f"(c[3])
        : "r"(a[0]), "r"(a[1]), "r"(a[2]), "r"(a[3]), "r"(b[0]), "r"(b[1]));
}
__device__ __forceinline__ void split16(float v, uint16_t& h, uint16_t& l) {
    __half hh = __float2half_rn(v);
    float  r  = v - __half2float(hh);
    __half ll = __float2half_rn(r);
    h = __half_as_ushort(hh);
    l = __half_as_ushort(ll);
}
__device__ __forceinline__ float actf(int aid, float z) {
    if (aid == 0) return z;
    if (aid == 1) return tanhf(z);
    if (aid == 2) return fmaxf(z, 0.f);
    return 1.f / (1.f + expf(-z));
}
__device__ __forceinline__ float readA(const char* hi, const char* lo, int m, int node) {
    uint32_t b = (uint32_t)m * (AS * 2) + (uint32_t)node * 2;
    return __half2float(*(const __half*)(hi + b)) + __half2float(*(const __half*)(lo + b));
}
// issue cp.async for W[0:Pn, nb:nb+16] -> stage. Chunk c (16B) handled by thread c%NTHREADS.
__device__ __forceinline__ void issueW(const float* __restrict__ W, int nb,
                                       uint32_t stage, int Pn, int tid) {
    const int nchunks = Pn * 4;
    for (int c = tid; c < nchunks; c += NTHREADS) {
        int p = c >> 2, s = c & 3;
        const float* src = W + (size_t)p * NN + nb + s * 4;
        asm volatile("cp.async.cg.shared.global [%0], [%1], 16;"
            :: "r"(stage + (uint32_t)p * 64 + (uint32_t)s * 16), "l"(src) : "memory");
    }
}
// convert staged fp32 W -> packed hi/lo fp16. SAME chunk->thread assignment as issueW,
// so each thread only reads bytes its own cp.asyncs wrote (self wait_group suffices).
__device__ __forceinline__ void convertW(const float* __restrict__ stg,
                                         char* bHi, char* bLo, int Pn, int tid) {
    const int nchunks = Pn * 4;
    for (int c = tid; c < nchunks; c += NTHREADS) {
        int p = c >> 2, s = c & 3;
        float4 v = *(const float4*)(stg + p * 16 + s * 4);
        float vv[4] = { v.x, v.y, v.z, v.w };
        #pragma unroll
        for (int i = 0; i < 4; ++i) {
            int n = s * 4 + i;
            uint16_t h, l; split16(vv[i], h, l);
            uint32_t byte = (((uint32_t)(p >> 1) * BPROW + n) << 2) + ((p & 1) << 1);
            *(uint16_t*)(bHi + byte) = h;
            *(uint16_t*)(bLo + byte) = l;
        }
    }
}

__global__ __launch_bounds__(NTHREADS, 1)
void scm_kernel(const float* __restrict__ causes,
                const float* __restrict__ W,
                const float* __restrict__ eps,
                const int*   __restrict__ act_ids,
                const int*   __restrict__ x_idx,
                const int*   __restrict__ y_idx_p,
                float*       __restrict__ out)
{
    extern __shared__ char smem[];
    const uint32_t sb = smem_u32(smem);
    int*  acts = (int*)(smem + OFF_ACTS);
    int*  xs   = (int*)(smem + OFF_XS);
    char* Ahi  = smem + OFF_AHI;
    char* Alo  = smem + OFF_ALO;

    const int tid  = threadIdx.x;
    const int lane = tid & 31;
    const int g    = lane >> 2;
    const int tig  = lane & 3;
    const int R    = (tid >> 5) * 16;
    const int row0 = blockIdx.x * ROWS;

    if (tid < NN) acts[tid] = act_ids[tid];
    if (tid < NF) xs[tid]   = x_idx[tid];

    // ---- roots: A[:, 0:32] = hi/lo split of clip(causes, -5, 5) ----
    {
        int m = tid >> 1, h = tid & 1;
        const float4* c4 = (const float4*)(causes + (size_t)(row0 + m) * NC + h * 16);
        float4 a = c4[0], b = c4[1], c = c4[2], d = c4[3];
        float v[16] = { a.x,a.y,a.z,a.w, b.x,b.y,b.z,b.w, c.x,c.y,c.z,c.w, d.x,d.y,d.z,d.w };
        uint32_t whi[8], wlo[8];
        #pragma unroll
        for (int i = 0; i < 8; ++i) {
            uint16_t h0, l0, h1, l1;
            float v0 = fminf(fmaxf(v[2*i],   -5.f), 5.f);
            float v1 = fminf(fmaxf(v[2*i+1], -5.f), 5.f);
            split16(v0, h0, l0); split16(v1, h1, l1);
            whi[i] = (uint32_t)h0 | ((uint32_t)h1 << 16);
            wlo[i] = (uint32_t)l0 | ((uint32_t)l1 << 16);
        }
        uint32_t base = (uint32_t)m * (AS * 2) + (uint32_t)h * 32;
        *(uint4*)(Ahi + base)      = make_uint4(whi[0], whi[1], whi[2], whi[3]);
        *(uint4*)(Ahi + base + 16) = make_uint4(whi[4], whi[5], whi[6], whi[7]);
        *(uint4*)(Alo + base)      = make_uint4(wlo[0], wlo[1], wlo[2], wlo[3]);
        *(uint4*)(Alo + base + 16) = make_uint4(wlo[4], wlo[5], wlo[6], wlo[7]);
    }

    // ---- pack layer-0 W directly; async-stage layer-1 W ----
    {
        char* bHi = smem + OFF_BP;
        char* bLo = bHi + BPHALF;
        for (int e = tid; e < NC * 16; e += NTHREADS) {
            int p = e >> 4, n = e & 15;
            uint16_t h, l; split16(W[(size_t)p * NN + NC + n], h, l);
            uint32_t byte = (((uint32_t)(p >> 1) * BPROW + n) << 2) + ((p & 1) << 1);
            *(uint16_t*)(bHi + byte) = h;
            *(uint16_t*)(bLo + byte) = l;
        }
        issueW(W, NC + LW, sb + OFF_STAGE + STAGEB, NC + LW, tid);   // W[1] -> stage[1]
        asm volatile("cp.async.commit_group;" ::: "memory");
    }
    __syncthreads();

    const uint32_t a_addr = sb + OFF_AHI
                          + (uint32_t)(R + (lane & 15)) * (AS * 2)
                          + (uint32_t)((lane >> 4) * 8) * 2;

    for (int k = 0; k < NL; ++k) {
        const int nb  = NC + k * LW;
        const int nch = nb >> 4;

        // async stage of W[k+2] -> stage[k&1]
        if (k < NL - 2) {
            const int nb2 = NC + (k + 2) * LW;
            issueW(W, nb2, sb + OFF_STAGE + (k & 1) * STAGEB, nb2, tid);
        }
        asm volatile("cp.async.commit_group;" ::: "memory");

        // prefetch eps for this layer's outputs
        float2 ev[4];
        #pragma unroll
        for (int t = 0; t < 2; ++t)
            #pragma unroll
            for (int hh = 0; hh < 2; ++hh)
                ev[t*2+hh] = *(const float2*)(eps + (size_t)(row0 + R + g + hh*8) * NN
                                              + nb + t*8 + 2*tig);

        const uint32_t* bpw = (const uint32_t*)(smem + OFF_BP + (k & 1) * BPBUF);
        const uint32_t* bpl = bpw + BPHALF / 4;

        // 6 independent accumulator chains (hh/hl/lh x n-halves)
        float chh0[4]={0,0,0,0}, chh1[4]={0,0,0,0};
        float chl0[4]={0,0,0,0}, chl1[4]={0,0,0,0};
        float clh0[4]={0,0,0,0}, clh1[4]={0,0,0,0};
        for (int j = 0; j < nch; ++j) {
            uint32_t ahi[4], alo[4];
            ldsm_x4(ahi, a_addr + j * 32);
            ldsm_x4(alo, a_addr + ABYTES + j * 32);
            const int kk = j * 8 + tig;
            uint32_t bh0[2], bh1[2], bl0[2], bl1[2];
            bh0[0] = bpw[kk * BPROW + g];           bh0[1] = bpw[(kk + 4) * BPROW + g];
            bh1[0] = bpw[kk * BPROW + 8 + g];       bh1[1] = bpw[(kk + 4) * BPROW + 8 + g];
            bl0[0] = bpl[kk * BPROW + g];           bl0[1] = bpl[(kk + 4) * BPROW + g];
            bl1[0] = bpl[kk * BPROW + 8 + g];       bl1[1] = bpl[(kk + 4) * BPROW + 8 + g];
            mma16816(chh0, ahi, bh0);  mma16816(chh1, ahi, bh1);
            mma16816(chl0, ahi, bl0);  mma16816(chl1, ahi, bl1);
            mma16816(clh0, alo, bh0);  mma16816(clh1, alo, bh1);
        }

        // convert staged W[k+1] -> packed B[(k+1)&1]; self-issued chunks only
        if (k < NL - 1) {
            asm volatile("cp.async.wait_group 1;" ::: "memory");
            char* bHi = smem + OFF_BP + ((k + 1) & 1) * BPBUF;
            convertW((const float*)(smem + OFF_STAGE + ((k + 1) & 1) * STAGEB),
                     bHi, bHi + BPHALF, nb + LW, tid);
        }

        // epilogue: z = C + eps, activation, hi/lo split, store back to A
        #pragma unroll
        for (int t = 0; t < 2; ++t) {
            float* ch = t ? chh1 : chh0;
            float* cl = t ? chl1 : chl0;
            float* ca = t ? clh1 : clh0;
            const int col0 = nb + t * 8 + 2 * tig;
            const int aid0 = acts[col0], aid1 = acts[col0 + 1];
            float z0 = ch[0] + (cl[0] + ca[0]) + ev[t*2].x;
            float z1 = ch[1] + (cl[1] + ca[1]) + ev[t*2].y;
            float z2 = ch[2] + (cl[2] + ca[2]) + ev[t*2+1].x;
            float z3 = ch[3] + (cl[3] + ca[3]) + ev[t*2+1].y;
            float a0 = actf(aid0, z0), a1 = actf(aid1, z1);
            float a2 = actf(aid0, z2), a3 = actf(aid1, z3);
            uint16_t h0,l0,h1,l1,h2,l2,h3,l3;
            split16(a0,h0,l0); split16(a1,h1,l1); split16(a2,h2,l2); split16(a3,h3,l3);
            uint32_t b0 = (uint32_t)(R + g)     * (AS * 2) + (uint32_t)col0 * 2;
            uint32_t b1 = (uint32_t)(R + g + 8) * (AS * 2) + (uint32_t)col0 * 2;
            *(uint32_t*)(Ahi + b0) = (uint32_t)h0 | ((uint32_t)h1 << 16);
            *(uint32_t*)(Alo + b0) = (uint32_t)l0 | ((uint32_t)l1 << 16);
            *(uint32_t*)(Ahi + b1) = (uint32_t)h2 | ((uint32_t)h3 << 16);
            *(uint32_t*)(Alo + b1) = (uint32_t)l2 | ((uint32_t)l3 << 16);
        }
        __syncthreads();
    }

    // ---- outputs ----
    const int yidx = y_idx_p ? *y_idx_p : (NN - 1);
    float* Xout = out;
    float* yout = out + (size_t)SEQ_LEN * NF;

    if (tid < ROWS) {
        float v = readA(Ahi, Alo, tid, yidx);
        if (v != v) v = 0.f;
        yout[row0 + tid] = v;
    }
    for (int idx = tid; idx < ROWS * NF; idx += NTHREADS) {
        int r = idx / NF, j = idx - r * NF;
        float v = readA(Ahi, Alo, r, xs[j]);
        if (v != v) v = 0.f;
        v = fminf(fmaxf(v, -15.f), 15.f);
        Xout[(size_t)(row0 + r) * NF + j] = v;
    }
}

extern "C" void kernel_launch(void* const* d_in, const int* in_sizes, int n_in,
                              void* d_out, int out_size)
{
    const float* causes  = (const float*)d_in[0];
    const float* W       = (const float*)d_in[1];
    const float* eps     = (const float*)d_in[2];
    const int*   act_ids = (const int*)d_in[3];
    const int*   x_idx   = (const int*)d_in[4];
    const int*   y_idx_p = (n_in > 5) ? (const int*)d_in[5] : nullptr;
    float*       out     = (float*)d_out;

    cudaFuncSetAttribute(scm_kernel, cudaFuncAttributeMaxDynamicSharedMemorySize, SMEM_BYTES);

    scm_kernel<<<SEQ_LEN / ROWS, NTHREADS, SMEM_BYTES>>>(
        causes, W, eps, act_ids, x_idx, y_idx_p, out);
    (void)in_sizes; (void)out_size;
}

// round 8
// speedup vs baseline: 1.8444x; 1.2185x over previous
#include <cuda_runtime.h>
#include <cuda_fp16.h>
#include <math.h>
#include <stdint.h>

// ---------------- problem constants ----------------
#define SEQ_LEN   65536
#define NN        256
#define NC        32
#define LW        16
#define NL        14
#define NF        200
#define ROWS      128      // M per CTA
#define NTHREADS  512      // 16 warps: 8 row-groups x 2 n-halves
#define AS        264      // A row stride in fp16 elems (528 B) -> conflict-free ldmatrix

// ---------------- smem map (bytes) ----------------
#define OFF_ACTS  0
#define OFF_XS    1024
#define OFF_BP    2048                      // 2 packed-W buffers x (hi + lo)
#define BPROW     24                        // u32 words per kk-row (16 used + pad)
#define BPHALF    (128 * BPROW * 4)         // 12288 B
#define BPBUF     (2 * BPHALF)
#define OFF_STAGE (OFF_BP + 2 * BPBUF)      // 2 x 16KB raw fp32 W stage (cp.async dst)
#define STAGEB    16384
#define OFF_AHI   (OFF_STAGE + 2 * STAGEB)
#define ABYTES    (ROWS * AS * 2)           // 67584
#define OFF_ALO   (OFF_AHI + ABYTES)
#define SMEM_BYTES (OFF_ALO + ABYTES)       // 219136

// ---------------- helpers ----------------
__device__ __forceinline__ uint32_t smem_u32(const void* p) {
    uint32_t a;
    asm("{ .reg .u64 t; cvta.to.shared.u64 t, %1; cvt.u32.u64 %0, t; }" : "=r"(a) : "l"(p));
    return a;
}
__device__ __forceinline__ void ldsm_x4(uint32_t a[4], uint32_t addr) {
    asm volatile("ldmatrix.sync.aligned.m8n8.x4.shared.b16 {%0,%1,%2,%3}, [%4];"
        : "=r"(a[0]), "=r"(a[1]), "=r"(a[2]), "=r"(a[3]) : "r"(addr));
}
__device__ __forceinline__ void mma16816(float c[4], const uint32_t a[4], const uint32_t b[2]) {
    asm volatile("mma.sync.aligned.m16n8k16.row.col.f32.f16.f16.f32 "
        "{%0,%1,%2,%3}, {%4,%5,%6,%7}, {%8,%9}, {%0,%1,%2,%3};"
        : "+f"(c[0]), "+f"(c[1]), "+f"(c[2]), "+f"(c[3])
        : "r"(a[0]), "r"(a[1]), "r"(a[2]), "r"(a[3]), "r"(b[0]), "r"(b[1]));
}
__device__ __forceinline__ void split16(float v, uint16_t& h, uint16_t& l) {
    __half hh = __float2half_rn(v);
    float  r  = v - __half2float(hh);
    __half ll = __float2half_rn(r);
    h = __half_as_ushort(hh);
    l = __half_as_ushort(ll);
}
__device__ __forceinline__ float ex2a(float x) {
    float r; asm("ex2.approx.f32 %0, %1;" : "=f"(r) : "f"(x)); return r;
}
__device__ __forceinline__ float rcpa(float x) {
    float r; asm("rcp.approx.f32 %0, %1;" : "=f"(r) : "f"(x)); return r;
}
__device__ __forceinline__ float actf(int aid, float z) {
    if (aid == 0) return z;
    if (aid == 2) return fmaxf(z, 0.f);
    if (aid == 1) {                       // tanh(z) = 1 - 2/(1+e^{2z})
        float t = ex2a(z * 2.8853900817779268f);   // 2*log2(e)
        return fmaf(-2.f, rcpa(t + 1.f), 1.f);
    }
    float t = ex2a(-z * 1.4426950408889634f);      // sigmoid
    return rcpa(1.f + t);
}
__device__ __forceinline__ float readA(const char* hi, const char* lo, int m, int node) {
    uint32_t b = (uint32_t)m * (AS * 2) + (uint32_t)node * 2;
    return __half2float(*(const __half*)(hi + b)) + __half2float(*(const __half*)(lo + b));
}
// issue cp.async for W[0:Pn, nb:nb+16] -> stage. Chunk c (16B) handled by thread c%NTHREADS.
__device__ __forceinline__ void issueW(const float* __restrict__ W, int nb,
                                       uint32_t stage, int Pn, int tid) {
    const int nchunks = Pn * 4;
    for (int c = tid; c < nchunks; c += NTHREADS) {
        int p = c >> 2, s = c & 3;
        const float* src = W + (size_t)p * NN + nb + s * 4;
        asm volatile("cp.async.cg.shared.global [%0], [%1], 16;"
            :: "r"(stage + (uint32_t)p * 64 + (uint32_t)s * 16), "l"(src) : "memory");
    }
}
// convert staged fp32 W -> packed hi/lo fp16. SAME chunk->thread map as issueW
// (each thread reads only bytes its own cp.asyncs wrote; self wait_group suffices).
__device__ __forceinline__ void convertW(const float* __restrict__ stg,
                                         char* bHi, char* bLo, int Pn, int tid) {
    const int nchunks = Pn * 4;
    for (int c = tid; c < nchunks; c += NTHREADS) {
        int p = c >> 2, s = c & 3;
        float4 v = *(const float4*)(stg + p * 16 + s * 4);
        float vv[4] = { v.x, v.y, v.z, v.w };
        #pragma unroll
        for (int i = 0; i < 4; ++i) {
            int n = s * 4 + i;
            uint16_t h, l; split16(vv[i], h, l);
            uint32_t byte = (((uint32_t)(p >> 1) * BPROW + n) << 2) + ((p & 1) << 1);
            *(uint16_t*)(bHi + byte) = h;
            *(uint16_t*)(bLo + byte) = l;
        }
    }
}

__global__ __launch_bounds__(NTHREADS, 1)
void scm_kernel(const float* __restrict__ causes,
                const float* __restrict__ W,
                const float* __restrict__ eps,
                const int*   __restrict__ act_ids,
                const int*   __restrict__ x_idx,
                const int*   __restrict__ y_idx_p,
                float*       __restrict__ out)
{
    extern __shared__ char smem[];
    const uint32_t sb = smem_u32(smem);
    int*  acts = (int*)(smem + OFF_ACTS);
    int*  xs   = (int*)(smem + OFF_XS);
    char* Ahi  = smem + OFF_AHI;
    char* Alo  = smem + OFF_ALO;

    const int tid  = threadIdx.x;
    const int lane = tid & 31;
    const int g    = lane >> 2;
    const int tig  = lane & 3;
    const int wid  = tid >> 5;
    const int rg   = wid & 7;          // row group 0..7
    const int nh   = wid >> 3;         // n-half 0/1
    const int R    = rg * 16;
    const int row0 = blockIdx.x * ROWS;

    if (tid < NN) acts[tid] = act_ids[tid];
    if (tid < NF) xs[tid]   = x_idx[tid];

    // ---- roots: A[:, 0:32] = hi/lo split of clip(causes, -5, 5) ----
    {
        int m = tid >> 2, q = tid & 3;          // 8 cols per thread
        const float4* c4 = (const float4*)(causes + (size_t)(row0 + m) * NC + q * 8);
        float4 a = c4[0], b = c4[1];
        float v[8] = { a.x,a.y,a.z,a.w, b.x,b.y,b.z,b.w };
        uint32_t whi[4], wlo[4];
        #pragma unroll
        for (int i = 0; i < 4; ++i) {
            uint16_t h0, l0, h1, l1;
            float v0 = fminf(fmaxf(v[2*i],   -5.f), 5.f);
            float v1 = fminf(fmaxf(v[2*i+1], -5.f), 5.f);
            split16(v0, h0, l0); split16(v1, h1, l1);
            whi[i] = (uint32_t)h0 | ((uint32_t)h1 << 16);
            wlo[i] = (uint32_t)l0 | ((uint32_t)l1 << 16);
        }
        uint32_t base = (uint32_t)m * (AS * 2) + (uint32_t)q * 16;
        *(uint4*)(Ahi + base) = make_uint4(whi[0], whi[1], whi[2], whi[3]);
        *(uint4*)(Alo + base) = make_uint4(wlo[0], wlo[1], wlo[2], wlo[3]);
    }

    // ---- pack layer-0 W directly; async-stage layer-1 W ----
    {
        char* bHi = smem + OFF_BP;
        char* bLo = bHi + BPHALF;
        for (int e = tid; e < NC * 16; e += NTHREADS) {
            int p = e >> 4, n = e & 15;
            uint16_t h, l; split16(W[(size_t)p * NN + NC + n], h, l);
            uint32_t byte = (((uint32_t)(p >> 1) * BPROW + n) << 2) + ((p & 1) << 1);
            *(uint16_t*)(bHi + byte) = h;
            *(uint16_t*)(bLo + byte) = l;
        }
        issueW(W, NC + LW, sb + OFF_STAGE + STAGEB, NC + LW, tid);   // W[1] -> stage[1]
        asm volatile("cp.async.commit_group;" ::: "memory");
    }
    __syncthreads();

    const uint32_t a_addr = sb + OFF_AHI
                          + (uint32_t)(R + (lane & 15)) * (AS * 2)
                          + (uint32_t)((lane >> 4) * 8) * 2;

    for (int k = 0; k < NL; ++k) {
        const int nb  = NC + k * LW;
        const int nch = nb >> 4;

        // async stage of W[k+2] -> stage[k&1]
        if (k < NL - 2) {
            const int nb2 = NC + (k + 2) * LW;
            issueW(W, nb2, sb + OFF_STAGE + (k & 1) * STAGEB, nb2, tid);
        }
        asm volatile("cp.async.commit_group;" ::: "memory");

        // prefetch eps for this warp's 16x8 output tile
        const int col0 = nb + nh * 8 + 2 * tig;
        float2 ev0 = *(const float2*)(eps + (size_t)(row0 + R + g)     * NN + col0);
        float2 ev1 = *(const float2*)(eps + (size_t)(row0 + R + g + 8) * NN + col0);

        const uint32_t* bpw = (const uint32_t*)(smem + OFF_BP + (k & 1) * BPBUF);
        const uint32_t* bpl = bpw + BPHALF / 4;
        const int bcol = nh * 8 + g;

        // 3 independent accumulator chains (hh / hl / lh), 16x8 tile
        float chh[4] = {0,0,0,0}, chl[4] = {0,0,0,0}, clh[4] = {0,0,0,0};
        for (int j = 0; j < nch; ++j) {
            uint32_t ahi[4], alo[4];
            ldsm_x4(ahi, a_addr + j * 32);
            ldsm_x4(alo, a_addr + ABYTES + j * 32);
            const int kk = j * 8 + tig;
            uint32_t bh[2], bl[2];
            bh[0] = bpw[kk * BPROW + bcol];  bh[1] = bpw[(kk + 4) * BPROW + bcol];
            bl[0] = bpl[kk * BPROW + bcol];  bl[1] = bpl[(kk + 4) * BPROW + bcol];
            mma16816(chh, ahi, bh);
            mma16816(chl, ahi, bl);
            mma16816(clh, alo, bh);
        }

        // convert staged W[k+1] -> packed B[(k+1)&1]; self-issued chunks only
        if (k < NL - 1) {
            asm volatile("cp.async.wait_group 1;" ::: "memory");
            char* bHi = smem + OFF_BP + ((k + 1) & 1) * BPBUF;
            convertW((const float*)(smem + OFF_STAGE + ((k + 1) & 1) * STAGEB),
                     bHi, bHi + BPHALF, nb + LW, tid);
        }

        // epilogue: z = C + eps, activation, hi/lo split, store back to A
        {
            const int aid0 = acts[col0], aid1 = acts[col0 + 1];
            float z0 = chh[0] + (chl[0] + clh[0]) + ev0.x;
            float z1 = chh[1] + (chl[1] + clh[1]) + ev0.y;
            float z2 = chh[2] + (chl[2] + clh[2]) + ev1.x;
            float z3 = chh[3] + (chl[3] + clh[3]) + ev1.y;
            float a0 = actf(aid0, z0), a1 = actf(aid1, z1);
            float a2 = actf(aid0, z2), a3 = actf(aid1, z3);
            uint16_t h0,l0,h1,l1,h2,l2,h3,l3;
            split16(a0,h0,l0); split16(a1,h1,l1); split16(a2,h2,l2); split16(a3,h3,l3);
            uint32_t b0 = (uint32_t)(R + g)     * (AS * 2) + (uint32_t)col0 * 2;
            uint32_t b1 = (uint32_t)(R + g + 8) * (AS * 2) + (uint32_t)col0 * 2;
            *(uint32_t*)(Ahi + b0) = (uint32_t)h0 | ((uint32_t)h1 << 16);
            *(uint32_t*)(Alo + b0) = (uint32_t)l0 | ((uint32_t)l1 << 16);
            *(uint32_t*)(Ahi + b1) = (uint32_t)h2 | ((uint32_t)h3 << 16);
            *(uint32_t*)(Alo + b1) = (uint32_t)l2 | ((uint32_t)l3 << 16);
        }
        __syncthreads();
    }

    // ---- outputs ----
    const int yidx = y_idx_p ? *y_idx_p : (NN - 1);
    float* Xout = out;
    float* yout = out + (size_t)SEQ_LEN * NF;

    if (tid < ROWS) {
        float v = readA(Ahi, Alo, tid, yidx);
        if (v != v) v = 0.f;
        yout[row0 + tid] = v;
    }
    for (int idx = tid; idx < ROWS * NF; idx += NTHREADS) {
        int r = idx / NF, j = idx - r * NF;
        float v = readA(Ahi, Alo, r, xs[j]);
        if (v != v) v = 0.f;
        v = fminf(fmaxf(v, -15.f), 15.f);
        Xout[(size_t)(row0 + r) * NF + j] = v;
    }
}

extern "C" void kernel_launch(void* const* d_in, const int* in_sizes, int n_in,
                              void* d_out, int out_size)
{
    const float* causes  = (const float*)d_in[0];
    const float* W       = (const float*)d_in[1];
    const float* eps     = (const float*)d_in[2];
    const int*   act_ids = (const int*)d_in[3];
    const int*   x_idx   = (const int*)d_in[4];
    const int*   y_idx_p = (n_in > 5) ? (const int*)d_in[5] : nullptr;
    float*       out     = (float*)d_out;

    cudaFuncSetAttribute(scm_kernel, cudaFuncAttributeMaxDynamicSharedMemorySize, SMEM_BYTES);

    scm_kernel<<<SEQ_LEN / ROWS, NTHREADS, SMEM_BYTES>>>(
        causes, W, eps, act_ids, x_idx, y_idx_p, out);
    (void)in_sizes; (void)out_size;
}